// round 7
// baseline (speedup 1.0000x reference)
#include <cuda_runtime.h>

#define B_   8
#define S_   32
#define D_   256
#define M_   2048
#define GPB  16      // blocks per batch
#define RPB  128     // rows per block
#define NT   256     // threads per block
#define PST  272     // floats per partial record
#define NBLK (B_*GPB)
#define NEGINF (__int_as_float(0xff800000))

// ----------------------------- device state -----------------------------
__device__ float g_mem [B_*M_*D_];        // per-batch working memory (written from regs at t=0)
__device__ float g_qt  [B_*S_*D_];        // (x@Wq+bq)@Wk^T / sqrt(D)
__device__ float g_xg  [B_*S_*D_];        // x@Wg1 + bg
__device__ float g_bgc [D_];              // bv@Wg2
__device__ float g_C   [D_*D_];           // Wv@Wg2
__device__ float g_part[2*B_*GPB*PST];    // partials, double buffered by step parity
__device__ int   g_tidx[2*B_*GPB*8];      // top8 global row ids
__device__ int   g_cnt [B_*S_];           // barrier-A counters (zeroed by init each launch)

__device__ __forceinline__ int ldacq(const int* p) {
    int v;
    asm volatile("ld.acquire.gpu.global.b32 %0, [%1];" : "=r"(v) : "l"(p) : "memory");
    return v;
}
// release-arrive without the L1D-flushing CCTL.IVALL of __threadfence()
__device__ __forceinline__ void red_release(int* p) {
    asm volatile("red.release.gpu.global.add.s32 [%0], %1;" :: "l"(p), "r"(1) : "memory");
}

// ----------------------------- init kernel (97 blocks) -----------------------------
//   [0,32)  : qt chain: tmpq = x@Wq+bq (smem), then qt = tmpq@Wk^T/sqrt(D)
//   [32,64) : g_xg = x@Wg1 + bg
//   [64,96) : g_C  = Wv@Wg2
//   96      : g_bgc = bv@Wg2 + zero barrier counters
__global__ void __launch_bounds__(NT)
mal_init(const float* __restrict__ x,  const float* __restrict__ Wq,
         const float* __restrict__ bq, const float* __restrict__ Wk,
         const float* __restrict__ Wv, const float* __restrict__ bv,
         const float* __restrict__ Wg, const float* __restrict__ bg)
{
    __shared__ float s_buf[2048];
    const int bid = blockIdx.x, tid = threadIdx.x;
    const int lane = tid & 31, warp = tid >> 5;

    if (bid == 96) {
        for (int i = tid; i < B_*S_; i += NT) g_cnt[i] = 0;
        float acc = 0.f;
        #pragma unroll 16
        for (int j = 0; j < D_; ++j) acc += bv[j] * Wg[(D_ + j)*D_ + tid];
        g_bgc[tid] = acc;
        return;
    }
    const int which = bid >> 5;               // 0: qt-chain, 1: xg, 2: C
    const int sub   = bid & 31;
    const int r0    = sub * 8;
    const float* srcA = (which == 2) ? (Wv + r0*D_) : (x + r0*D_);
    for (int i = tid; i < 2048; i += NT) s_buf[i] = srcA[i];
    __syncthreads();
    const float* Wcol = (which == 0) ? Wq : (which == 1 ? Wg : (Wg + D_*D_));
    float acc[8];
    #pragma unroll
    for (int r = 0; r < 8; ++r) acc[r] = 0.f;
    #pragma unroll 16
    for (int j = 0; j < D_; ++j) {
        float w = Wcol[j*D_ + tid];
        #pragma unroll
        for (int r = 0; r < 8; ++r) acc[r] += s_buf[r*D_ + j] * w;
    }
    if (which == 1) {
        float bb = bg[tid];
        #pragma unroll
        for (int r = 0; r < 8; ++r) g_xg[(r0+r)*D_ + tid] = acc[r] + bb;
    } else if (which == 2) {
        #pragma unroll
        for (int r = 0; r < 8; ++r) g_C[(r0+r)*D_ + tid] = acc[r];
    } else {
        // tmpq -> smem, then qt = tmpq @ Wk^T / sqrt(D)
        float bb = bq[tid];
        __syncthreads();
        #pragma unroll
        for (int r = 0; r < 8; ++r) s_buf[r*D_ + tid] = acc[r] + bb;
        __syncthreads();
        float4 t0[8], t1[8];
        #pragma unroll
        for (int r = 0; r < 8; ++r) {
            t0[r] = *(const float4*)(s_buf + r*D_ + lane*4);
            t1[r] = *(const float4*)(s_buf + r*D_ + 128 + lane*4);
        }
        int d = warp * 32;
        float4 w0 = *(const float4*)(Wk + d*D_ + lane*4);
        float4 w1 = *(const float4*)(Wk + d*D_ + 128 + lane*4);
        for (int dd = 0; dd < 32; ++dd) {
            float4 c0 = w0, c1 = w1;
            if (dd < 31) {
                w0 = *(const float4*)(Wk + (d+1)*D_ + lane*4);
                w1 = *(const float4*)(Wk + (d+1)*D_ + 128 + lane*4);
            }
            float dt[8];
            #pragma unroll
            for (int r = 0; r < 8; ++r) {
                dt[r] = t0[r].x*c0.x + t0[r].y*c0.y + t0[r].z*c0.z + t0[r].w*c0.w
                      + t1[r].x*c1.x + t1[r].y*c1.y + t1[r].z*c1.z + t1[r].w*c1.w;
                #pragma unroll
                for (int o = 16; o; o >>= 1) dt[r] += __shfl_xor_sync(0xffffffffu, dt[r], o);
            }
            if (lane == 0) {
                #pragma unroll
                for (int r = 0; r < 8; ++r) g_qt[(r0+r)*D_ + d] = dt[r] * 0.0625f;
            }
            ++d;
        }
    }
}

// ----------------------------- main persistent kernel -----------------------------
__global__ void __launch_bounds__(NT, 1)
mal_main(const float* __restrict__ x, const float* __restrict__ memory,
         const float* __restrict__ Wv, const float* __restrict__ bv,
         float* __restrict__ out)
{
    __shared__ float s_wacc[8][D_];
    __shared__ float s_q[D_];
    __shared__ float s_lg[128];
    __shared__ float s_e[128];
    __shared__ float s_r8[8];
    __shared__ float s_cv[128];
    __shared__ int   s_ci[128];
    __shared__ unsigned long long s_pk[128];
    __shared__ int   s_rk[NT];
    __shared__ int   s_sel[8];
    __shared__ float s_p[D_];
    __shared__ float s_red[NT];
    __shared__ float s_scale[16];
    __shared__ float s_bm, s_invS;

    const int tid  = threadIdx.x, lane = tid & 31, warp = tid >> 5;
    const int bid  = blockIdx.x;
    const int b    = bid >> 4;
    const int blk  = bid & 15;
    int* cA        = g_cnt + b * S_;
    const int d0   = lane * 4;
    const int d1   = 128 + lane * 4;
    const int rbase = blk * RPB + warp * 16;
    const float* bMem = memory + rbase * D_;              // shared across batches (t=0 only)
    float* bG         = g_mem + (b*M_ + rbase) * D_;      // per-batch (t>0)

    for (int t = 0; t < S_; ++t) {
        const int buf  = t & 1;
        float* part    = g_part + buf*(B_*GPB*PST) + bid * PST;
        int*   tidx    = g_tidx + buf*(B_*GPB*8);

        s_q[tid] = g_qt[(b*S_ + t)*D_ + tid];
        __syncthreads();

        // ---- pass 1: own 128 rows -> regs, all 128 logits ----
        const float q0 = s_q[d0],   q1 = s_q[d0+1], q2 = s_q[d0+2], q3 = s_q[d0+3];
        const float q4 = s_q[d1],   q5 = s_q[d1+1], q6 = s_q[d1+2], q7 = s_q[d1+3];
        const float* rowp = (t == 0) ? bMem : bG;
        float4 ra[16], rb[16];
        #pragma unroll
        for (int r = 0; r < 16; ++r) {
            ra[r] = *(const float4*)(rowp + r*D_ + d0);
            rb[r] = *(const float4*)(rowp + r*D_ + d1);
            float dt = ra[r].x*q0 + ra[r].y*q1 + ra[r].z*q2 + ra[r].w*q3
                     + rb[r].x*q4 + rb[r].y*q5 + rb[r].z*q6 + rb[r].w*q7;
            #pragma unroll
            for (int o = 16; o; o >>= 1) dt += __shfl_xor_sync(0xffffffffu, dt, o);
            if (lane == 0) s_lg[warp*16 + r] = dt;
        }
        // t=0: populate per-batch working memory straight from registers
        if (t == 0) {
            #pragma unroll
            for (int r = 0; r < 16; ++r) {
                *(float4*)(bG + r*D_ + d0) = ra[r];
                *(float4*)(bG + r*D_ + d1) = rb[r];
            }
        }
        __syncthreads();

        // ---- block max, exp table, per-warp sums, packed keys ----
        float v = (tid < 128) ? s_lg[tid] : NEGINF;
        {
            float m = v;
            #pragma unroll
            for (int o = 16; o; o >>= 1) m = fmaxf(m, __shfl_xor_sync(0xffffffffu, m, o));
            if (lane == 0) s_r8[warp] = m;
        }
        __syncthreads();
        if (tid == 0) {
            float bm = s_r8[0];
            #pragma unroll
            for (int w = 1; w < 8; ++w) bm = fmaxf(bm, s_r8[w]);
            s_bm = bm;
        }
        __syncthreads();
        const float bm = s_bm;
        float e = (tid < 128) ? __expf(v - bm) : 0.f;
        if (tid < 128) s_e[tid] = e;
        {
            float se = e;
            #pragma unroll
            for (int o = 16; o; o >>= 1) se += __shfl_xor_sync(0xffffffffu, se, o);
            if (lane == 0) s_r8[warp] = se;
        }
        if (tid < 128) {
            unsigned fb = __float_as_uint(v);
            fb ^= (fb & 0x80000000u) ? 0xFFFFFFFFu : 0x80000000u;
            s_pk[tid] = ((unsigned long long)fb << 32) | (unsigned)(~tid);
        }
        __syncthreads();

        // ---- pass 2: weighted row sum from registers + split local rank ----
        {
            float4 A = {0,0,0,0}, Bb = {0,0,0,0};
            #pragma unroll
            for (int r = 0; r < 16; ++r) {
                float er = s_e[warp*16 + r];
                A.x += er*ra[r].x; A.y += er*ra[r].y; A.z += er*ra[r].z; A.w += er*ra[r].w;
                Bb.x += er*rb[r].x; Bb.y += er*rb[r].y; Bb.z += er*rb[r].z; Bb.w += er*rb[r].w;
            }
            *(float4*)&s_wacc[warp][d0] = A;
            *(float4*)&s_wacc[warp][d1] = Bb;
        }
        {
            const int c  = tid & 127;
            const int j0 = (tid >> 7) * 64;
            unsigned long long me = s_pk[c];
            int rk = 0;
            #pragma unroll 16
            for (int j = 0; j < 64; ++j) rk += (s_pk[j0 + j] > me);
            s_rk[tid] = rk;
        }
        __syncthreads();
        {
            float pv = 0.f;
            #pragma unroll
            for (int w = 0; w < 8; ++w) pv += s_wacc[w][tid];
            part[2 + tid] = pv;
            if (tid == 0) {
                float sw = 0.f;
                #pragma unroll
                for (int w = 0; w < 8; ++w) sw += s_r8[w];
                part[0] = bm; part[1] = sw;
            }
        }
        if (tid < 128) {
            int rk = s_rk[tid] + s_rk[tid + 128];
            if (rk < 8) {
                part[258 + rk] = s_lg[tid];
                tidx[bid*8 + rk] = blk*RPB + tid;
            }
        }
        __syncthreads();
        // ---- single global barrier per step ----
        if (tid == 0) {
            red_release(&cA[t]);
            while (ldacq(&cA[t]) < GPB) { }
        }
        __syncthreads();

        // ---- merge 16 partials (redundant per block) ----
        if (warp == 0) {
            float bmv = (lane < 16) ? __ldcg(&g_part[buf*(B_*GPB*PST) + (b*GPB + lane)*PST])     : NEGINF;
            float swv = (lane < 16) ? __ldcg(&g_part[buf*(B_*GPB*PST) + (b*GPB + lane)*PST + 1]) : 0.f;
            float Mx = bmv;
            #pragma unroll
            for (int o = 16; o; o >>= 1) Mx = fmaxf(Mx, __shfl_xor_sync(0xffffffffu, Mx, o));
            float sc = (lane < 16) ? __expf(bmv - Mx) : 0.f;
            if (lane < 16) s_scale[lane] = sc;
            float Ssum = sc * swv;
            #pragma unroll
            for (int o = 16; o; o >>= 1) Ssum += __shfl_xor_sync(0xffffffffu, Ssum, o);
            if (lane == 0) s_invS = 1.0f / Ssum;
        } else if (warp >= 4) {
            int ii = tid - 128;
            int i = ii >> 3, j = ii & 7;
            s_cv[ii] = __ldcg(&g_part[buf*(B_*GPB*PST) + (b*GPB + i)*PST + 258 + j]);
            s_ci[ii] = __ldcg(&g_tidx[buf*(B_*GPB*8) + (b*GPB + i)*8 + j]);
        }
        __syncthreads();
        {
            float pv = 0.f;
            #pragma unroll
            for (int i = 0; i < 16; ++i)
                pv += __ldcg(&g_part[buf*(B_*GPB*PST) + (b*GPB + i)*PST + 2 + tid]) * s_scale[i];
            s_p[tid] = pv * s_invS;
        }
        if (tid < 128) {
            unsigned fb = __float_as_uint(s_cv[tid]);
            fb ^= (fb & 0x80000000u) ? 0xFFFFFFFFu : 0x80000000u;
            s_pk[tid] = ((unsigned long long)fb << 32) | (unsigned)(~s_ci[tid]);
        }
        __syncthreads();

        // ---- global top-8 rank overlapped with out-slice GEMV ----
        {
            const int c  = tid & 127;
            const int j0 = (tid >> 7) * 64;
            unsigned long long me = s_pk[c];
            int rk = 0;
            #pragma unroll 16
            for (int j = 0; j < 64; ++j) rk += (s_pk[j0 + j] > me);
            s_rk[tid] = rk;
        }
        {
            const int dbase = blk * 16;
            const int col = tid & 15, k0 = (tid >> 4) * 16;
            float acc = 0.f;
            #pragma unroll
            for (int kk = 0; kk < 16; ++kk)
                acc += s_p[k0 + kk] * Wv[(k0 + kk)*D_ + dbase + col];
            s_red[tid] = acc;
        }
        __syncthreads();
        if (tid < 128) {
            int rk = s_rk[tid] + s_rk[tid + 128];
            if (rk < 8) s_sel[rk] = s_ci[tid];
        }
        if (tid < 16) {
            float tot = 0.f;
            #pragma unroll
            for (int s = 0; s < 16; ++s) tot += s_red[s*16 + tid];
            const int dbase = blk * 16;
            out[(b*S_ + t)*D_ + dbase + tid] = tot + __ldg(&bv[dbase + tid]);
        }
        __syncthreads();

        // ---- owner blocks: compute full gate vector locally, update rows now ----
        if (t < S_ - 1) {
            bool own = false;
            #pragma unroll
            for (int k = 0; k < 8; ++k) own |= ((s_sel[k] >> 7) == blk);
            if (own) {
                float z = g_xg[(b*S_ + t)*D_ + tid] + g_bgc[tid];
                #pragma unroll 8
                for (int k = 0; k < D_; ++k) z += s_p[k] * g_C[k*D_ + tid];
                float gt = 1.0f / (1.0f + __expf(-z));
                float xd = __ldg(&x[(b*S_ + t)*D_ + tid]);
                float keep = 1.0f - gt, add = gt * xd;
                #pragma unroll
                for (int k = 0; k < 8; ++k) {
                    int gi = s_sel[k];
                    if ((gi >> 7) == blk) {
                        float* row = g_mem + (b*M_ + gi)*D_;
                        row[tid] = keep * row[tid] + add;
                    }
                }
            }
        }
        __syncthreads();
    }
}

// ----------------------------- launch -----------------------------
extern "C" void kernel_launch(void* const* d_in, const int* in_sizes, int n_in,
                              void* d_out, int out_size)
{
    const float* x      = (const float*)d_in[0];
    const float* memory = (const float*)d_in[1];
    const float* Wq     = (const float*)d_in[2];
    const float* bq     = (const float*)d_in[3];
    const float* Wk     = (const float*)d_in[4];
    // d_in[5] = bk : constant logit shift; softmax/top-k invariant -> unused
    const float* Wv     = (const float*)d_in[6];
    const float* bv     = (const float*)d_in[7];
    const float* Wg     = (const float*)d_in[8];
    const float* bg     = (const float*)d_in[9];
    float* out = (float*)d_out;

    mal_init<<<97, NT>>>(x, Wq, bq, Wk, Wv, bv, Wg, bg);
    mal_main<<<NBLK, NT>>>(x, memory, Wv, bv, out);
}

// round 8
// speedup vs baseline: 1.5820x; 1.5820x over previous
#include <cuda_runtime.h>

#define B_   8
#define S_   32
#define D_   256
#define M_   2048
#define GPB  16      // blocks per batch
#define RPB  128     // rows per block
#define NT   256     // threads per block
#define PST  272     // floats per partial record
#define NBLK (B_*GPB)
#define NEGINF (__int_as_float(0xff800000))

// ----------------------------- device state -----------------------------
__device__ float g_mem [B_*M_*D_];        // per-batch working memory (filled from regs at t=0)
__device__ float g_qt  [B_*S_*D_];        // (x@Wq+bq)@Wk^T / sqrt(D)
__device__ float g_xg  [B_*S_*D_];        // x@Wg1 + bg
__device__ float g_bgc [D_];              // bv@Wg2
__device__ float g_C   [D_*D_];           // Wv@Wg2
__device__ float g_part[2*B_*GPB*PST];    // partials, double buffered by step parity
__device__ int   g_tidx[2*B_*GPB*8];      // top8 global row ids
__device__ float g_gv  [B_*D_];           // gate vector per batch
__device__ int   g_cnt [2*B_*S_];         // cA[256] then cB[256], zeroed by init

__device__ __forceinline__ int ldacq(const int* p) {
    int v;
    asm volatile("ld.acquire.gpu.global.b32 %0, [%1];" : "=r"(v) : "l"(p) : "memory");
    return v;
}
// release-arrive without the L1D-flushing CCTL.IVALL of __threadfence()
__device__ __forceinline__ void red_release(int* p) {
    asm volatile("red.release.gpu.global.add.s32 [%0], %1;" :: "l"(p), "r"(1) : "memory");
}

// ----------------------------- init kernel (97 blocks) -----------------------------
__global__ void __launch_bounds__(NT)
mal_init(const float* __restrict__ x,  const float* __restrict__ Wq,
         const float* __restrict__ bq, const float* __restrict__ Wk,
         const float* __restrict__ Wv, const float* __restrict__ bv,
         const float* __restrict__ Wg, const float* __restrict__ bg)
{
    __shared__ float s_buf[2048];
    const int bid = blockIdx.x, tid = threadIdx.x;
    const int lane = tid & 31, warp = tid >> 5;

    if (bid == 96) {
        for (int i = tid; i < 2*B_*S_; i += NT) g_cnt[i] = 0;
        float acc = 0.f;
        #pragma unroll 16
        for (int j = 0; j < D_; ++j) acc += bv[j] * Wg[(D_ + j)*D_ + tid];
        g_bgc[tid] = acc;
        return;
    }
    const int which = bid >> 5;               // 0: qt-chain, 1: xg, 2: C
    const int sub   = bid & 31;
    const int r0    = sub * 8;
    const float* srcA = (which == 2) ? (Wv + r0*D_) : (x + r0*D_);
    for (int i = tid; i < 2048; i += NT) s_buf[i] = srcA[i];
    __syncthreads();
    const float* Wcol = (which == 0) ? Wq : (which == 1 ? Wg : (Wg + D_*D_));
    float acc[8];
    #pragma unroll
    for (int r = 0; r < 8; ++r) acc[r] = 0.f;
    #pragma unroll 16
    for (int j = 0; j < D_; ++j) {
        float w = Wcol[j*D_ + tid];
        #pragma unroll
        for (int r = 0; r < 8; ++r) acc[r] += s_buf[r*D_ + j] * w;
    }
    if (which == 1) {
        float bb = bg[tid];
        #pragma unroll
        for (int r = 0; r < 8; ++r) g_xg[(r0+r)*D_ + tid] = acc[r] + bb;
    } else if (which == 2) {
        #pragma unroll
        for (int r = 0; r < 8; ++r) g_C[(r0+r)*D_ + tid] = acc[r];
    } else {
        float bb = bq[tid];
        __syncthreads();
        #pragma unroll
        for (int r = 0; r < 8; ++r) s_buf[r*D_ + tid] = acc[r] + bb;
        __syncthreads();
        float4 t0[8], t1[8];
        #pragma unroll
        for (int r = 0; r < 8; ++r) {
            t0[r] = *(const float4*)(s_buf + r*D_ + lane*4);
            t1[r] = *(const float4*)(s_buf + r*D_ + 128 + lane*4);
        }
        int d = warp * 32;
        float4 w0 = *(const float4*)(Wk + d*D_ + lane*4);
        float4 w1 = *(const float4*)(Wk + d*D_ + 128 + lane*4);
        for (int dd = 0; dd < 32; ++dd) {
            float4 c0 = w0, c1 = w1;
            if (dd < 31) {
                w0 = *(const float4*)(Wk + (d+1)*D_ + lane*4);
                w1 = *(const float4*)(Wk + (d+1)*D_ + 128 + lane*4);
            }
            float dt[8];
            #pragma unroll
            for (int r = 0; r < 8; ++r) {
                dt[r] = t0[r].x*c0.x + t0[r].y*c0.y + t0[r].z*c0.z + t0[r].w*c0.w
                      + t1[r].x*c1.x + t1[r].y*c1.y + t1[r].z*c1.z + t1[r].w*c1.w;
                #pragma unroll
                for (int o = 16; o; o >>= 1) dt[r] += __shfl_xor_sync(0xffffffffu, dt[r], o);
            }
            if (lane == 0) {
                #pragma unroll
                for (int r = 0; r < 8; ++r) g_qt[(r0+r)*D_ + d] = dt[r] * 0.0625f;
            }
            ++d;
        }
    }
}

// ----------------------------- main persistent kernel -----------------------------
__global__ void __launch_bounds__(NT, 1)
mal_main(const float* __restrict__ x, const float* __restrict__ memory,
         const float* __restrict__ Wv, const float* __restrict__ bv,
         float* __restrict__ out)
{
    __shared__ float s_wacc[8][D_];
    __shared__ float s_wm[8], s_ws[8];
    __shared__ float s_lg[128];
    __shared__ unsigned long long s_pk[128];
    __shared__ int   s_rk[NT];
    __shared__ int   s_ci[128];
    __shared__ int   s_sel[8];
    __shared__ float s_p[D_];
    __shared__ float s_red[NT];

    const int tid  = threadIdx.x, lane = tid & 31, warp = tid >> 5;
    const int bid  = blockIdx.x;
    const int b    = bid >> 4;
    const int blk  = bid & 15;
    int* cA        = g_cnt + b * S_;
    int* cB        = g_cnt + B_*S_ + b * S_;
    const int d0   = lane * 4;
    const int d1   = 128 + lane * 4;
    const int rbase = blk * RPB + warp * 16;
    const float* bMem = memory + rbase * D_;          // t=0 source (shared across batches)
    float* bG         = g_mem + (b*M_ + rbase) * D_;  // per-batch working rows

    for (int t = 0; t < S_; ++t) {
        const int buf  = t & 1;
        float* partbase = g_part + buf*(B_*GPB*PST);
        float* part     = partbase + bid * PST;
        int*   tidx     = g_tidx + buf*(B_*GPB*8);

        // ---- owner blocks apply previous step's gated updates ----
        if (t > 0) {
            bool own = false;
            #pragma unroll
            for (int k = 0; k < 8; ++k) own |= ((s_sel[k] >> 7) == blk);
            if (own) {                                  // block-uniform branch
                if (tid == 0) { while (ldacq(&cB[t-1]) < GPB) { } }
                __syncthreads();
                float gd   = __ldcg(&g_gv[b*D_ + tid]);
                float xd   = __ldg(&x[(b*S_ + (t-1))*D_ + tid]);
                float keep = 1.0f - gd, add = gd * xd;
                #pragma unroll
                for (int k = 0; k < 8; ++k) {
                    int gi = s_sel[k];
                    if ((gi >> 7) == blk) {
                        float* row = g_mem + (b*M_ + gi)*D_;
                        row[tid] = keep * row[tid] + add;
                    }
                }
                __syncthreads();
            }
        }

        // ---- q straight to registers (no smem staging) ----
        const float4 qa = *(const float4*)(g_qt + (b*S_ + t)*D_ + d0);
        const float4 qb = *(const float4*)(g_qt + (b*S_ + t)*D_ + d1);

        // ---- pass 1: own 128 rows -> regs, warp-uniform logits ----
        const float* rowp = (t == 0) ? bMem : bG;
        float4 ra[16], rb[16];
        float dts[16];
        float mw = NEGINF;
        #pragma unroll
        for (int r = 0; r < 16; ++r) {
            ra[r] = *(const float4*)(rowp + r*D_ + d0);
            rb[r] = *(const float4*)(rowp + r*D_ + d1);
            float dt = ra[r].x*qa.x + ra[r].y*qa.y + ra[r].z*qa.z + ra[r].w*qa.w
                     + rb[r].x*qb.x + rb[r].y*qb.y + rb[r].z*qb.z + rb[r].w*qb.w;
            #pragma unroll
            for (int o = 16; o; o >>= 1) dt += __shfl_xor_sync(0xffffffffu, dt, o);
            dts[r] = dt;
            mw = fmaxf(mw, dt);
            if (lane == 0) s_lg[warp*16 + r] = dt;
        }
        if (t == 0) {
            #pragma unroll
            for (int r = 0; r < 16; ++r) {
                *(float4*)(bG + r*D_ + d0) = ra[r];
                *(float4*)(bG + r*D_ + d1) = rb[r];
            }
        }

        // ---- pass 2 (warp-local, unnormalized vs warp max; NO sync needed) ----
        {
            float sw = 0.f;
            float4 A = {0,0,0,0}, Bb = {0,0,0,0};
            #pragma unroll
            for (int r = 0; r < 16; ++r) {
                float e = __expf(dts[r] - mw);
                sw += e;
                A.x += e*ra[r].x; A.y += e*ra[r].y; A.z += e*ra[r].z; A.w += e*ra[r].w;
                Bb.x += e*rb[r].x; Bb.y += e*rb[r].y; Bb.z += e*rb[r].z; Bb.w += e*rb[r].w;
            }
            *(float4*)&s_wacc[warp][d0] = A;
            *(float4*)&s_wacc[warp][d1] = Bb;
            if (lane == 0) { s_wm[warp] = mw; s_ws[warp] = sw; }
        }
        __syncthreads();                                            // S1

        // ---- stage 2: every thread computes bm + rescaled partial ----
        {
            float m0 = fmaxf(fmaxf(s_wm[0], s_wm[1]), fmaxf(s_wm[2], s_wm[3]));
            float m1 = fmaxf(fmaxf(s_wm[4], s_wm[5]), fmaxf(s_wm[6], s_wm[7]));
            float bm = fmaxf(m0, m1);
            float sc[8];
            #pragma unroll
            for (int w = 0; w < 8; ++w) sc[w] = __expf(s_wm[w] - bm);
            float pv = 0.f;
            #pragma unroll
            for (int w = 0; w < 8; ++w) pv += s_wacc[w][tid] * sc[w];
            part[2 + tid] = pv;
            if (tid == 0) {
                float sw = 0.f;
                #pragma unroll
                for (int w = 0; w < 8; ++w) sw += s_ws[w] * sc[w];
                part[0] = bm; part[1] = sw;
            }
            if (tid < 128) {
                unsigned fb = __float_as_uint(s_lg[tid]);
                fb ^= (fb & 0x80000000u) ? 0xFFFFFFFFu : 0x80000000u;
                s_pk[tid] = ((unsigned long long)fb << 32) | (unsigned)(~tid);
            }
        }
        __syncthreads();                                            // S2

        // ---- local top-8 rank (split 2x64) ----
        {
            const int c  = tid & 127;
            const int j0 = (tid >> 7) * 64;
            unsigned long long me = s_pk[c];
            int rk = 0;
            #pragma unroll 16
            for (int j = 0; j < 64; ++j) rk += (s_pk[j0 + j] > me);
            s_rk[tid] = rk;
        }
        __syncthreads();                                            // S3
        if (tid < 128) {
            int rk = s_rk[tid] + s_rk[tid + 128];
            if (rk < 8) {
                part[258 + rk] = s_lg[tid];
                tidx[bid*8 + rk] = blk*RPB + tid;
            }
        }
        __syncthreads();                                            // S4
        // ---- global barrier A ----
        if (tid == 0) {
            red_release(&cA[t]);
            while (ldacq(&cA[t]) < GPB) { }
        }
        __syncthreads();                                            // S5

        // ---- merge: every thread computes scales itself ----
        {
            float bmv[16], swv[16];
            #pragma unroll
            for (int i = 0; i < 16; ++i) {
                bmv[i] = __ldcg(&partbase[(b*GPB + i)*PST]);
                swv[i] = __ldcg(&partbase[(b*GPB + i)*PST + 1]);
            }
            float Mx = bmv[0];
            #pragma unroll
            for (int i = 1; i < 16; ++i) Mx = fmaxf(Mx, bmv[i]);
            float Ssum = 0.f, sc[16];
            #pragma unroll
            for (int i = 0; i < 16; ++i) { sc[i] = __expf(bmv[i] - Mx); Ssum += sc[i]*swv[i]; }
            float invS = 1.0f / Ssum;
            float pv = 0.f;
            #pragma unroll
            for (int i = 0; i < 16; ++i)
                pv += __ldcg(&partbase[(b*GPB + i)*PST + 2 + tid]) * sc[i];
            s_p[tid] = pv * invS;
        }
        if (tid < 128) {
            int i = tid >> 3, j = tid & 7;
            float cv = __ldcg(&partbase[(b*GPB + i)*PST + 258 + j]);
            int   ci = __ldcg(&g_tidx[buf*(B_*GPB*8) + (b*GPB + i)*8 + j]);
            s_ci[tid] = ci;
            unsigned fb = __float_as_uint(cv);
            fb ^= (fb & 0x80000000u) ? 0xFFFFFFFFu : 0x80000000u;
            s_pk[tid] = ((unsigned long long)fb << 32) | (unsigned)(~ci);
        }
        __syncthreads();                                            // S6

        // ---- global top-8 rank overlapped with out/gate slice GEMV ----
        {
            const int c  = tid & 127;
            const int j0 = (tid >> 7) * 64;
            unsigned long long me = s_pk[c];
            int rk = 0;
            #pragma unroll 16
            for (int j = 0; j < 64; ++j) rk += (s_pk[j0 + j] > me);
            s_rk[tid] = rk;
        }
        {
            const int dbase = blk * 16;
            const float* Mp = (lane < 16) ? (Wv + dbase + lane)
                                          : (g_C + dbase + (lane - 16));
            float acc = 0.f;
            const int k0 = warp * 32;
            #pragma unroll
            for (int kk = 0; kk < 32; ++kk)
                acc += s_p[k0 + kk] * Mp[(k0 + kk)*D_];
            s_red[tid] = acc;
        }
        __syncthreads();                                            // S7
        if (tid < 128) {
            int rk = s_rk[tid] + s_rk[tid + 128];
            if (rk < 8) s_sel[rk] = s_ci[tid];
        }
        if (tid < 32) {
            float tot = 0.f;
            #pragma unroll
            for (int w = 0; w < 8; ++w) tot += s_red[w*32 + tid];
            const int dbase = blk * 16;
            if (tid < 16) {
                out[(b*S_ + t)*D_ + dbase + tid] = tot + __ldg(&bv[dbase + tid]);
            } else {
                int d = dbase + tid - 16;
                float z = g_xg[(b*S_ + t)*D_ + d] + g_bgc[d] + tot;
                g_gv[b*D_ + d] = 1.0f / (1.0f + __expf(-z));
            }
        }
        __syncthreads();                                            // S8
        if (tid == 0) red_release(&cB[t]);   // owners wait at t+1
    }
}

// ----------------------------- launch -----------------------------
extern "C" void kernel_launch(void* const* d_in, const int* in_sizes, int n_in,
                              void* d_out, int out_size)
{
    const float* x      = (const float*)d_in[0];
    const float* memory = (const float*)d_in[1];
    const float* Wq     = (const float*)d_in[2];
    const float* bq     = (const float*)d_in[3];
    const float* Wk     = (const float*)d_in[4];
    // d_in[5] = bk : constant logit shift; softmax/top-k invariant -> unused
    const float* Wv     = (const float*)d_in[6];
    const float* bv     = (const float*)d_in[7];
    const float* Wg     = (const float*)d_in[8];
    const float* bg     = (const float*)d_in[9];
    float* out = (float*)d_out;

    mal_init<<<97, NT>>>(x, Wq, bq, Wk, Wv, bv, Wg, bg);
    mal_main<<<NBLK, NT>>>(x, memory, Wv, bv, out);
}

// round 9
// speedup vs baseline: 1.5934x; 1.0072x over previous
#include <cuda_runtime.h>

#define B_   8
#define S_   32
#define D_   256
#define M_   2048
#define GPB  16      // blocks per batch
#define RPB  128     // rows per block
#define NT   256     // threads per block
#define PST  272     // floats per partial record
#define NBLK (B_*GPB)
#define ROWS_BYTES (RPB*D_*4)   // 128 KB dynamic smem: this block's memory rows
#define NEGINF (__int_as_float(0xff800000))

// ----------------------------- device state -----------------------------
__device__ float g_qt  [B_*S_*D_];        // (x@Wq+bq)@Wk^T / sqrt(D)
__device__ float g_xg  [B_*S_*D_];        // x@Wg1 + bg
__device__ float g_bgc [D_];              // bv@Wg2
__device__ float g_C   [D_*D_];           // Wv@Wg2
__device__ float g_part[2*B_*GPB*PST];    // partials, double buffered by step parity
__device__ int   g_tidx[2*B_*GPB*8];      // top8 global row ids
__device__ float g_gv  [B_*D_];           // gate vector per batch
__device__ int   g_cnt [2*B_*S_];         // cA[256] then cB[256], zeroed by init

__device__ __forceinline__ int ldacq(const int* p) {
    int v;
    asm volatile("ld.acquire.gpu.global.b32 %0, [%1];" : "=r"(v) : "l"(p) : "memory");
    return v;
}
// release-arrive without the L1D-flushing CCTL.IVALL of __threadfence()
__device__ __forceinline__ void red_release(int* p) {
    asm volatile("red.release.gpu.global.add.s32 [%0], %1;" :: "l"(p), "r"(1) : "memory");
}

// ----------------------------- init kernel (97 blocks) -----------------------------
__global__ void __launch_bounds__(NT)
mal_init(const float* __restrict__ x,  const float* __restrict__ Wq,
         const float* __restrict__ bq, const float* __restrict__ Wk,
         const float* __restrict__ Wv, const float* __restrict__ bv,
         const float* __restrict__ Wg, const float* __restrict__ bg)
{
    __shared__ float s_buf[2048];
    const int bid = blockIdx.x, tid = threadIdx.x;
    const int lane = tid & 31, warp = tid >> 5;

    if (bid == 96) {
        for (int i = tid; i < 2*B_*S_; i += NT) g_cnt[i] = 0;
        float acc = 0.f;
        #pragma unroll 16
        for (int j = 0; j < D_; ++j) acc += bv[j] * Wg[(D_ + j)*D_ + tid];
        g_bgc[tid] = acc;
        return;
    }
    const int which = bid >> 5;               // 0: qt-chain, 1: xg, 2: C
    const int sub   = bid & 31;
    const int r0    = sub * 8;
    const float* srcA = (which == 2) ? (Wv + r0*D_) : (x + r0*D_);
    for (int i = tid; i < 2048; i += NT) s_buf[i] = srcA[i];
    __syncthreads();
    const float* Wcol = (which == 0) ? Wq : (which == 1 ? Wg : (Wg + D_*D_));
    float acc[8];
    #pragma unroll
    for (int r = 0; r < 8; ++r) acc[r] = 0.f;
    #pragma unroll 16
    for (int j = 0; j < D_; ++j) {
        float w = Wcol[j*D_ + tid];
        #pragma unroll
        for (int r = 0; r < 8; ++r) acc[r] += s_buf[r*D_ + j] * w;
    }
    if (which == 1) {
        float bb = bg[tid];
        #pragma unroll
        for (int r = 0; r < 8; ++r) g_xg[(r0+r)*D_ + tid] = acc[r] + bb;
    } else if (which == 2) {
        #pragma unroll
        for (int r = 0; r < 8; ++r) g_C[(r0+r)*D_ + tid] = acc[r];
    } else {
        float bb = bq[tid];
        __syncthreads();
        #pragma unroll
        for (int r = 0; r < 8; ++r) s_buf[r*D_ + tid] = acc[r] + bb;
        __syncthreads();
        float4 t0[8], t1[8];
        #pragma unroll
        for (int r = 0; r < 8; ++r) {
            t0[r] = *(const float4*)(s_buf + r*D_ + lane*4);
            t1[r] = *(const float4*)(s_buf + r*D_ + 128 + lane*4);
        }
        int d = warp * 32;
        float4 w0 = *(const float4*)(Wk + d*D_ + lane*4);
        float4 w1 = *(const float4*)(Wk + d*D_ + 128 + lane*4);
        for (int dd = 0; dd < 32; ++dd) {
            float4 c0 = w0, c1 = w1;
            if (dd < 31) {
                w0 = *(const float4*)(Wk + (d+1)*D_ + lane*4);
                w1 = *(const float4*)(Wk + (d+1)*D_ + 128 + lane*4);
            }
            float dt[8];
            #pragma unroll
            for (int r = 0; r < 8; ++r) {
                dt[r] = t0[r].x*c0.x + t0[r].y*c0.y + t0[r].z*c0.z + t0[r].w*c0.w
                      + t1[r].x*c1.x + t1[r].y*c1.y + t1[r].z*c1.z + t1[r].w*c1.w;
                #pragma unroll
                for (int o = 16; o; o >>= 1) dt[r] += __shfl_xor_sync(0xffffffffu, dt[r], o);
            }
            if (lane == 0) {
                #pragma unroll
                for (int r = 0; r < 8; ++r) g_qt[(r0+r)*D_ + d] = dt[r] * 0.0625f;
            }
            ++d;
        }
    }
}

// ----------------------------- main persistent kernel -----------------------------
__global__ void __launch_bounds__(NT, 1)
mal_main(const float* __restrict__ x, const float* __restrict__ memory,
         const float* __restrict__ Wv, const float* __restrict__ bv,
         float* __restrict__ out)
{
    extern __shared__ float s_rows[];     // [RPB][D_]  this block's 128 memory rows
    __shared__ float s_wacc[8][D_];
    __shared__ float s_wm[8], s_ws[8];
    __shared__ float s_lg[128];
    __shared__ unsigned long long s_pk[128];
    __shared__ int   s_rk[NT];
    __shared__ int   s_ci[128];
    __shared__ int   s_sel[8];
    __shared__ float s_p[D_];
    __shared__ float s_red[NT];

    const int tid  = threadIdx.x, lane = tid & 31, warp = tid >> 5;
    const int bid  = blockIdx.x;
    const int b    = bid >> 4;
    const int blk  = bid & 15;
    int* cA        = g_cnt + b * S_;
    int* cB        = g_cnt + B_*S_ + b * S_;
    const int d0   = lane * 4;
    const int d1   = 128 + lane * 4;
    const float* bMem = memory + (blk*RPB + warp*16) * D_;  // t=0 source
    float* srow       = s_rows + (warp*16) * D_;            // this warp's 16 rows

    for (int t = 0; t < S_; ++t) {
        const int buf  = t & 1;
        float* partbase = g_part + buf*(B_*GPB*PST);
        float* part     = partbase + bid * PST;
        int*   tidx     = g_tidx + buf*(B_*GPB*8);

        // ---- owner blocks apply previous step's gated updates (smem rows) ----
        if (t > 0) {
            bool own = false;
            #pragma unroll
            for (int k = 0; k < 8; ++k) own |= ((s_sel[k] >> 7) == blk);
            if (own) {                                  // block-uniform branch
                if (tid == 0) { while (ldacq(&cB[t-1]) < GPB) { } }
                __syncthreads();
                float gd   = __ldcg(&g_gv[b*D_ + tid]);
                float xd   = __ldg(&x[(b*S_ + (t-1))*D_ + tid]);
                float keep = 1.0f - gd, add = gd * xd;
                #pragma unroll
                for (int k = 0; k < 8; ++k) {
                    int gi = s_sel[k];
                    if ((gi >> 7) == blk) {
                        float* row = s_rows + (gi & 127)*D_;
                        row[tid] = keep * row[tid] + add;
                    }
                }
                __syncthreads();
            }
        }

        // ---- q straight to registers ----
        const float4 qa = *(const float4*)(g_qt + (b*S_ + t)*D_ + d0);
        const float4 qb = *(const float4*)(g_qt + (b*S_ + t)*D_ + d1);

        // ---- pass 1: own 16 rows (per warp) -> regs, warp-uniform logits ----
        float4 ra[16], rb[16];
        float dts[16];
        float mw = NEGINF;
        if (t == 0) {
            #pragma unroll
            for (int r = 0; r < 16; ++r) {
                ra[r] = *(const float4*)(bMem + r*D_ + d0);
                rb[r] = *(const float4*)(bMem + r*D_ + d1);
                *(float4*)(srow + r*D_ + d0) = ra[r];
                *(float4*)(srow + r*D_ + d1) = rb[r];
                float dt = ra[r].x*qa.x + ra[r].y*qa.y + ra[r].z*qa.z + ra[r].w*qa.w
                         + rb[r].x*qb.x + rb[r].y*qb.y + rb[r].z*qb.z + rb[r].w*qb.w;
                #pragma unroll
                for (int o = 16; o; o >>= 1) dt += __shfl_xor_sync(0xffffffffu, dt, o);
                dts[r] = dt;
                mw = fmaxf(mw, dt);
                if (lane == 0) s_lg[warp*16 + r] = dt;
            }
        } else {
            #pragma unroll
            for (int r = 0; r < 16; ++r) {
                ra[r] = *(const float4*)(srow + r*D_ + d0);
                rb[r] = *(const float4*)(srow + r*D_ + d1);
                float dt = ra[r].x*qa.x + ra[r].y*qa.y + ra[r].z*qa.z + ra[r].w*qa.w
                         + rb[r].x*qb.x + rb[r].y*qb.y + rb[r].z*qb.z + rb[r].w*qb.w;
                #pragma unroll
                for (int o = 16; o; o >>= 1) dt += __shfl_xor_sync(0xffffffffu, dt, o);
                dts[r] = dt;
                mw = fmaxf(mw, dt);
                if (lane == 0) s_lg[warp*16 + r] = dt;
            }
        }

        // ---- pass 2 (warp-local, unnormalized vs warp max; no sync needed) ----
        {
            float sw = 0.f;
            float4 A = {0,0,0,0}, Bb = {0,0,0,0};
            #pragma unroll
            for (int r = 0; r < 16; ++r) {
                float e = __expf(dts[r] - mw);
                sw += e;
                A.x += e*ra[r].x; A.y += e*ra[r].y; A.z += e*ra[r].z; A.w += e*ra[r].w;
                Bb.x += e*rb[r].x; Bb.y += e*rb[r].y; Bb.z += e*rb[r].z; Bb.w += e*rb[r].w;
            }
            *(float4*)&s_wacc[warp][d0] = A;
            *(float4*)&s_wacc[warp][d1] = Bb;
            if (lane == 0) { s_wm[warp] = mw; s_ws[warp] = sw; }
        }
        __syncthreads();                                            // S1

        // ---- stage 2: every thread computes bm + rescaled partial ----
        {
            float m0 = fmaxf(fmaxf(s_wm[0], s_wm[1]), fmaxf(s_wm[2], s_wm[3]));
            float m1 = fmaxf(fmaxf(s_wm[4], s_wm[5]), fmaxf(s_wm[6], s_wm[7]));
            float bm = fmaxf(m0, m1);
            float sc[8];
            #pragma unroll
            for (int w = 0; w < 8; ++w) sc[w] = __expf(s_wm[w] - bm);
            float pv = 0.f;
            #pragma unroll
            for (int w = 0; w < 8; ++w) pv += s_wacc[w][tid] * sc[w];
            part[2 + tid] = pv;
            if (tid == 0) {
                float sw = 0.f;
                #pragma unroll
                for (int w = 0; w < 8; ++w) sw += s_ws[w] * sc[w];
                part[0] = bm; part[1] = sw;
            }
            if (tid < 128) {
                unsigned fb = __float_as_uint(s_lg[tid]);
                fb ^= (fb & 0x80000000u) ? 0xFFFFFFFFu : 0x80000000u;
                s_pk[tid] = ((unsigned long long)fb << 32) | (unsigned)(~tid);
            }
        }
        __syncthreads();                                            // S2

        // ---- local top-8 rank (split 2x64) ----
        {
            const int c  = tid & 127;
            const int j0 = (tid >> 7) * 64;
            unsigned long long me = s_pk[c];
            int rk = 0;
            #pragma unroll 16
            for (int j = 0; j < 64; ++j) rk += (s_pk[j0 + j] > me);
            s_rk[tid] = rk;
        }
        __syncthreads();                                            // S3
        if (tid < 128) {
            int rk = s_rk[tid] + s_rk[tid + 128];
            if (rk < 8) {
                part[258 + rk] = s_lg[tid];
                tidx[bid*8 + rk] = blk*RPB + tid;
            }
        }
        __syncthreads();                                            // S4
        // ---- global barrier A ----
        if (tid == 0) {
            red_release(&cA[t]);
            while (ldacq(&cA[t]) < GPB) { }
        }
        __syncthreads();                                            // S5

        // ---- merge: every thread computes scales itself ----
        {
            float bmv[16], swv[16];
            #pragma unroll
            for (int i = 0; i < 16; ++i) {
                bmv[i] = __ldcg(&partbase[(b*GPB + i)*PST]);
                swv[i] = __ldcg(&partbase[(b*GPB + i)*PST + 1]);
            }
            float Mx = bmv[0];
            #pragma unroll
            for (int i = 1; i < 16; ++i) Mx = fmaxf(Mx, bmv[i]);
            float Ssum = 0.f, sc[16];
            #pragma unroll
            for (int i = 0; i < 16; ++i) { sc[i] = __expf(bmv[i] - Mx); Ssum += sc[i]*swv[i]; }
            float invS = 1.0f / Ssum;
            float pv = 0.f;
            #pragma unroll
            for (int i = 0; i < 16; ++i)
                pv += __ldcg(&partbase[(b*GPB + i)*PST + 2 + tid]) * sc[i];
            s_p[tid] = pv * invS;
        }
        if (tid < 128) {
            int i = tid >> 3, j = tid & 7;
            float cv = __ldcg(&partbase[(b*GPB + i)*PST + 258 + j]);
            int   ci = __ldcg(&g_tidx[buf*(B_*GPB*8) + (b*GPB + i)*8 + j]);
            s_ci[tid] = ci;
            unsigned fb = __float_as_uint(cv);
            fb ^= (fb & 0x80000000u) ? 0xFFFFFFFFu : 0x80000000u;
            s_pk[tid] = ((unsigned long long)fb << 32) | (unsigned)(~ci);
        }
        __syncthreads();                                            // S6

        // ---- global top-8 rank overlapped with out/gate slice GEMV ----
        {
            const int c  = tid & 127;
            const int j0 = (tid >> 7) * 64;
            unsigned long long me = s_pk[c];
            int rk = 0;
            #pragma unroll 16
            for (int j = 0; j < 64; ++j) rk += (s_pk[j0 + j] > me);
            s_rk[tid] = rk;
        }
        {
            const int dbase = blk * 16;
            const float* Mp = (lane < 16) ? (Wv + dbase + lane)
                                          : (g_C + dbase + (lane - 16));
            float acc = 0.f;
            const int k0 = warp * 32;
            #pragma unroll
            for (int kk = 0; kk < 32; ++kk)
                acc += s_p[k0 + kk] * Mp[(k0 + kk)*D_];
            s_red[tid] = acc;
        }
        __syncthreads();                                            // S7
        if (tid < 128) {
            int rk = s_rk[tid] + s_rk[tid + 128];
            if (rk < 8) s_sel[rk] = s_ci[tid];
        }
        if (tid < 32) {
            float tot = 0.f;
            #pragma unroll
            for (int w = 0; w < 8; ++w) tot += s_red[w*32 + tid];
            const int dbase = blk * 16;
            if (tid < 16) {
                out[(b*S_ + t)*D_ + dbase + tid] = tot + __ldg(&bv[dbase + tid]);
            } else {
                int d = dbase + tid - 16;
                float z = g_xg[(b*S_ + t)*D_ + d] + g_bgc[d] + tot;
                g_gv[b*D_ + d] = 1.0f / (1.0f + __expf(-z));
            }
        }
        __syncthreads();                                            // S8
        if (tid == 0) red_release(&cB[t]);   // owners wait at t+1
    }
}

// ----------------------------- launch -----------------------------
extern "C" void kernel_launch(void* const* d_in, const int* in_sizes, int n_in,
                              void* d_out, int out_size)
{
    const float* x      = (const float*)d_in[0];
    const float* memory = (const float*)d_in[1];
    const float* Wq     = (const float*)d_in[2];
    const float* bq     = (const float*)d_in[3];
    const float* Wk     = (const float*)d_in[4];
    // d_in[5] = bk : constant logit shift; softmax/top-k invariant -> unused
    const float* Wv     = (const float*)d_in[6];
    const float* bv     = (const float*)d_in[7];
    const float* Wg     = (const float*)d_in[8];
    const float* bg     = (const float*)d_in[9];
    float* out = (float*)d_out;

    cudaFuncSetAttribute(mal_main, cudaFuncAttributeMaxDynamicSharedMemorySize, ROWS_BYTES);
    mal_init<<<97, NT>>>(x, Wq, bq, Wk, Wv, bv, Wg, bg);
    mal_main<<<NBLK, NT, ROWS_BYTES>>>(x, memory, Wv, bv, out);
}